// round 4
// baseline (speedup 1.0000x reference)
#include <cuda_runtime.h>

// out[n, i] = b[n, i] * sum_j a[n, j],  B = L = 8192, fp32.
// Split into two kernels so the big (2/3-of-traffic) scale kernel is
// completely dependency- and barrier-free:
//   A: rowsum[n] = sum_j a[n, j]     (pure 256MB read)
//   B: out[n,i]  = b[n,i]*rowsum[n]  (pure 512MB mixed stream, no barriers)

constexpr int L = 8192;
constexpr int THREADS = 256;
constexpr int VECS_PER_ROW = L / 4;             // 2048 float4
constexpr int VPT = VECS_PER_ROW / THREADS;     // 8 per thread
constexpr int ROWS = 8192;

__device__ float g_rowsum[ROWS];                // scratch (no allocs allowed)

// ---- Kernel A: block-per-row reduction of a ----
__global__ __launch_bounds__(THREADS)
void rowsum_kernel(const float* __restrict__ a)
{
    const int row = blockIdx.x;
    const int tid = threadIdx.x;
    const float4* a4 = reinterpret_cast<const float4*>(a) + (size_t)row * VECS_PER_ROW;

    float s0 = 0.f, s1 = 0.f, s2 = 0.f, s3 = 0.f;
    #pragma unroll
    for (int i = 0; i < VPT; i++) {
        float4 v = __ldcs(&a4[tid + i * THREADS]);
        s0 += v.x; s1 += v.y; s2 += v.z; s3 += v.w;
    }
    float s = (s0 + s1) + (s2 + s3);

    #pragma unroll
    for (int off = 16; off > 0; off >>= 1)
        s += __shfl_xor_sync(0xFFFFFFFFu, s, off);

    __shared__ float warp_sums[THREADS / 32];
    if ((tid & 31) == 0) warp_sums[tid >> 5] = s;
    __syncthreads();

    if (tid == 0) {
        float t = 0.f;
        #pragma unroll
        for (int w = 0; w < THREADS / 32; w++) t += warp_sums[w];
        g_rowsum[row] = t;
    }
}

// ---- Kernel B: out = b * rowsum[row]; barrier-free pure stream ----
__global__ __launch_bounds__(THREADS)
void scale_kernel(const float* __restrict__ b, float* __restrict__ out)
{
    const int row = blockIdx.x;
    const int tid = threadIdx.x;

    const float scale = __ldg(&g_rowsum[row]);  // L2-broadcast, one 4B load

    const float4* b4 = reinterpret_cast<const float4*>(b) + (size_t)row * VECS_PER_ROW;
    float4* o4       = reinterpret_cast<float4*>(out)     + (size_t)row * VECS_PER_ROW;

    #pragma unroll
    for (int i = 0; i < VPT; i++) {
        float4 v = __ldcs(&b4[tid + i * THREADS]);
        v.x *= scale; v.y *= scale; v.z *= scale; v.w *= scale;
        __stcs(&o4[tid + i * THREADS], v);
    }
}

extern "C" void kernel_launch(void* const* d_in, const int* in_sizes, int n_in,
                              void* d_out, int out_size)
{
    const float* a = (const float*)d_in[0];
    const float* b = (const float*)d_in[1];
    float* out = (float*)d_out;

    rowsum_kernel<<<ROWS, THREADS>>>(a);
    scale_kernel<<<ROWS, THREADS>>>(b, out);
}

// round 5
// speedup vs baseline: 1.0933x; 1.0933x over previous
#include <cuda_runtime.h>

// out[n, i] = b[n, i] * sum_j a[n, j],  B = L = 8192, fp32.
// R1 fused shape (best: 2:1 read:write mix, regs=32, 8 CTAs/SM) made
// PERSISTENT: grid = 152 SMs * 8 CTAs, each CTA loops over rows with
// grid stride. Removes ~6 wave transitions and launch-tail raggedness.

constexpr int L = 8192;
constexpr int THREADS = 256;
constexpr int VECS_PER_ROW = L / 4;             // 2048 float4
constexpr int VPT = VECS_PER_ROW / THREADS;     // 8 per thread
constexpr int ROWS = 8192;
constexpr int SMS = 152;                        // GB300
constexpr int CTAS_PER_SM = 8;                  // 64-warp cap at 256 threads
constexpr int GRID = SMS * CTAS_PER_SM;         // 1216

__global__ __launch_bounds__(THREADS, CTAS_PER_SM)
void outer_product_rowscale(const float* __restrict__ a,
                            const float* __restrict__ b,
                            float* __restrict__ out)
{
    __shared__ float warp_sums[THREADS / 32];
    __shared__ float row_sum;

    const int tid = threadIdx.x;

    for (int row = blockIdx.x; row < ROWS; row += GRID) {
        const float4* a4 = reinterpret_cast<const float4*>(a) + (size_t)row * VECS_PER_ROW;
        const float4* b4 = reinterpret_cast<const float4*>(b) + (size_t)row * VECS_PER_ROW;
        float4* o4       = reinterpret_cast<float4*>(out)     + (size_t)row * VECS_PER_ROW;

        // ---- Phase 1: row-sum of a (coalesced, streaming) ----
        float s0 = 0.f, s1 = 0.f, s2 = 0.f, s3 = 0.f;
        #pragma unroll
        for (int i = 0; i < VPT; i++) {
            float4 v = __ldcs(&a4[tid + i * THREADS]);
            s0 += v.x; s1 += v.y; s2 += v.z; s3 += v.w;
        }
        float s = (s0 + s1) + (s2 + s3);

        #pragma unroll
        for (int off = 16; off > 0; off >>= 1)
            s += __shfl_xor_sync(0xFFFFFFFFu, s, off);

        if ((tid & 31) == 0) warp_sums[tid >> 5] = s;
        __syncthreads();

        if (tid == 0) {
            float t = 0.f;
            #pragma unroll
            for (int w = 0; w < THREADS / 32; w++) t += warp_sums[w];
            row_sum = t;
        }
        __syncthreads();

        const float scale = row_sum;

        // ---- Phase 2: out = b * scale (streaming) ----
        #pragma unroll
        for (int i = 0; i < VPT; i++) {
            float4 v = __ldcs(&b4[tid + i * THREADS]);
            v.x *= scale; v.y *= scale; v.z *= scale; v.w *= scale;
            __stcs(&o4[tid + i * THREADS], v);
        }

        // Barrier before reusing row_sum/warp_sums next iteration.
        __syncthreads();
    }
}

extern "C" void kernel_launch(void* const* d_in, const int* in_sizes, int n_in,
                              void* d_out, int out_size)
{
    const float* a = (const float*)d_in[0];
    const float* b = (const float*)d_in[1];
    float* out = (float*)d_out;

    outer_product_rowscale<<<GRID, THREADS>>>(a, b, out);
}

// round 6
// speedup vs baseline: 1.1160x; 1.0207x over previous
#include <cuda_runtime.h>

// out[n, i] = b[n, i] * sum_j a[n, j],  B = L = 8192, fp32.
// R1 shape (fused, CTA-per-row, 8 CTAs/SM) + two refinements:
//  1. single-barrier reduction (all threads redundantly sum 8 warp partials)
//  2. prefetch first 2 b-vectors before the reduction to hide barrier-exit
//     DRAM latency. __launch_bounds__(256,8) pins the 32-reg/8-CTA budget.

constexpr int L = 8192;
constexpr int THREADS = 256;
constexpr int NWARPS = THREADS / 32;            // 8
constexpr int VECS_PER_ROW = L / 4;             // 2048 float4
constexpr int VPT = VECS_PER_ROW / THREADS;     // 8 per thread

__global__ __launch_bounds__(THREADS, 8)
void outer_product_rowscale(const float* __restrict__ a,
                            const float* __restrict__ b,
                            float* __restrict__ out)
{
    __shared__ float warp_sums[NWARPS];         // 8 floats = 2 x float4

    const int row = blockIdx.x;
    const int tid = threadIdx.x;

    const float4* a4 = reinterpret_cast<const float4*>(a) + (size_t)row * VECS_PER_ROW;
    const float4* b4 = reinterpret_cast<const float4*>(b) + (size_t)row * VECS_PER_ROW;
    float4* o4       = reinterpret_cast<float4*>(out)     + (size_t)row * VECS_PER_ROW;

    // ---- Phase 1: row-sum of a (coalesced, streaming) ----
    float s0 = 0.f, s1 = 0.f, s2 = 0.f, s3 = 0.f;
    #pragma unroll
    for (int i = 0; i < VPT; i++) {
        float4 v = __ldcs(&a4[tid + i * THREADS]);
        s0 += v.x; s1 += v.y; s2 += v.z; s3 += v.w;
    }
    float s = (s0 + s1) + (s2 + s3);

    // Prefetch first two b vectors: in flight across the reduce + barrier.
    float4 p0 = __ldcs(&b4[tid]);
    float4 p1 = __ldcs(&b4[tid + THREADS]);

    // warp reduce
    #pragma unroll
    for (int off = 16; off > 0; off >>= 1)
        s += __shfl_xor_sync(0xFFFFFFFFu, s, off);

    if ((tid & 31) == 0) warp_sums[tid >> 5] = s;
    __syncthreads();                             // single barrier

    // Every thread sums the 8 partials itself (broadcast LDS, conflict-free).
    const float4 w0 = *reinterpret_cast<const float4*>(&warp_sums[0]);
    const float4 w1 = *reinterpret_cast<const float4*>(&warp_sums[4]);
    const float scale = ((w0.x + w0.y) + (w0.z + w0.w))
                      + ((w1.x + w1.y) + (w1.z + w1.w));

    // ---- Phase 2: out = b * scale ----
    p0.x *= scale; p0.y *= scale; p0.z *= scale; p0.w *= scale;
    __stcs(&o4[tid], p0);
    p1.x *= scale; p1.y *= scale; p1.z *= scale; p1.w *= scale;
    __stcs(&o4[tid + THREADS], p1);

    #pragma unroll
    for (int i = 2; i < VPT; i++) {
        float4 v = __ldcs(&b4[tid + i * THREADS]);
        v.x *= scale; v.y *= scale; v.z *= scale; v.w *= scale;
        __stcs(&o4[tid + i * THREADS], v);
    }
}

extern "C" void kernel_launch(void* const* d_in, const int* in_sizes, int n_in,
                              void* d_out, int out_size)
{
    const float* a = (const float*)d_in[0];
    const float* b = (const float*)d_in[1];
    float* out = (float*)d_out;

    const int rows = in_sizes[0] / L;            // 8192
    outer_product_rowscale<<<rows, THREADS>>>(a, b, out);
}